// round 8
// baseline (speedup 1.0000x reference)
#include <cuda_runtime.h>

typedef unsigned long long u64;

#define THREADS 256
#define WT_BYTES 36864                 // 2 loc * 72 pp * 32 u64
#define XT_OFF   36864
#define XT_STRIDE 34                   // u64 per pp row (32 b + 2 pad, even -> 16B align)
#define XT_BYTES (2 * 72 * XT_STRIDE * 8)     // 39168
#define BS_OFF   (XT_OFF + XT_BYTES)   // 76032
#define SMEM_BYTES (BS_OFF + 256)      // 76288
#define GAT_OFF  32768                 // bytes; after 4*1024 u64 reduction buf

__device__ __forceinline__ void fma2(u64& d, u64 a, u64 b) {
    asm("fma.rn.f32x2 %0, %1, %2, %0;" : "+l"(d) : "l"(a), "l"(b));
}
__device__ __forceinline__ u64 add2(u64 a, u64 b) {
    u64 r; asm("add.rn.f32x2 %0, %1, %2;" : "=l"(r) : "l"(a), "l"(b)); return r;
}
__device__ __forceinline__ void unpackf2(u64 d, float& lo, float& hi) {
    asm("mov.b64 {%0, %1}, %2;" : "=f"(lo), "=f"(hi) : "l"(d));
}

__global__ __launch_bounds__(THREADS, 2) void xonv_kernel(
    const float* __restrict__ x,        // (32, 16, 64, 64)
    const float* __restrict__ weights,  // (64, 64, 32, 16, 3, 3)
    const float* __restrict__ bias,     // (64, 64, 32)
    float* __restrict__ out)            // (32, 32, 64, 64)
{
    extern __shared__ __align__(16) char sm[];
    u64*   wT = (u64*)sm;                         // [(l*72+pp)*32 + (sigma(o)+pp)&31]
    u64*   xT = (u64*)(sm + XT_OFF);              // [(l*72+pp)*34 + b]
    float* bs = (float*)(sm + BS_OFF);

    const int tid  = threadIdx.x;
    const int lane = tid & 31;
    const int wid  = tid >> 5;
    const int h    = blockIdx.x >> 5;
    const int w0   = (blockIdx.x & 31) * 2;
    const int loc0 = h * 64 + w0;

    // ---------- stage weights: coalesced LDG.64, STS into swizzled transposed layout ----
    {
        const float2* wg2 = (const float2*)weights;
        #pragma unroll
        for (int i = 0; i < 18; ++i) {
            int g  = tid + THREADS * i;            // 0..4607 = (l, o, pp), pp fastest
            int pp = g % 72;
            int rest = g / 72;
            int oo = rest & 31;
            int l  = rest >> 5;
            float2 v = wg2[((size_t)(loc0 + l) * 32 + oo) * 72 + pp];
            int sig = ((oo & 3) << 3) | (oo >> 2);
            u64 bits;
            asm("mov.b64 %0, {%1, %2};" : "=l"(bits) : "f"(v.x), "f"(v.y));
            wT[(l * 72 + pp) * 32 + ((sig + pp) & 31)] = bits;
        }
    }
    if (tid < 64) bs[tid] = bias[(size_t)loc0 * 32 + tid];

    // ---------- stage x: expanded p-major per loc, floats into xT u64 halves ----------
    {
        float* xf = (float*)xT;
        const int dr = lane >> 2;                  // 0..7
        const int c  = lane & 3;                   // ww = w0 + c - 1
        #pragma unroll 4
        for (int it = 0; it < 24; ++it) {
            int r  = it * 64 + wid * 8 + dr;       // 0..1535 = b*48 + ck
            int b  = r / 48;
            int ck = r - b * 48;
            int ci = ck / 3;
            int kh = ck - ci * 3;
            int hh = h + kh - 1;
            int ww = w0 + c - 1;
            float v = 0.f;
            if ((unsigned)hh < 64u && (unsigned)ww < 64u)
                v = x[(((size_t)b * 16 + ci) * 64 + hh) * 64 + ww];
            // value feeds loc l with kw = c - l, if 0 <= kw <= 2
            if (c <= 2) {                           // l = 0
                int p = 3 * ck + c;
                xf[((0 * 72 + (p >> 1)) * XT_STRIDE + b) * 2 + (p & 1)] = v;
            }
            if (c >= 1) {                           // l = 1
                int p = 3 * ck + (c - 1);
                xf[((1 * 72 + (p >> 1)) * XT_STRIDE + b) * 2 + (p & 1)] = v;
            }
        }
    }
    __syncthreads();

    // ---------- compute: warp = (loc l, K-quarter kq); lane = (bg<<3)|og; tile 8b x 4o --
    const int l  = wid >> 2;
    const int kq = wid & 3;
    const int bg = lane >> 3;                      // 0..3  (b = bg*8 + jb)
    const int og = lane & 7;                       // 0..7  (o = og*4 + m)

    const u64* xrow = xT + (l * 72 + kq * 18) * XT_STRIDE + bg * 8;
    const u64* wrow = wT + (l * 72 + kq * 18) * 32;
    int rot = (og + kq * 18) & 31;                 // (og + pp) & 31

    u64 acc[32];                                   // [jb*4 + m]
    #pragma unroll
    for (int j = 0; j < 32; ++j) acc[j] = 0ull;

    #pragma unroll 2
    for (int i = 0; i < 18; ++i) {
        u64 wv0 = wrow[rot];
        u64 wv1 = wrow[(rot + 8)  & 31];
        u64 wv2 = wrow[(rot + 16) & 31];
        u64 wv3 = wrow[(rot + 24) & 31];
        ulonglong2 xa = *(const ulonglong2*)(xrow);
        ulonglong2 xb = *(const ulonglong2*)(xrow + 2);
        ulonglong2 xc = *(const ulonglong2*)(xrow + 4);
        ulonglong2 xd = *(const ulonglong2*)(xrow + 6);
        u64 xv[8] = {xa.x, xa.y, xb.x, xb.y, xc.x, xc.y, xd.x, xd.y};
        #pragma unroll
        for (int jb = 0; jb < 8; ++jb) {
            fma2(acc[jb * 4 + 0], xv[jb], wv0);
            fma2(acc[jb * 4 + 1], xv[jb], wv1);
            fma2(acc[jb * 4 + 2], xv[jb], wv2);
            fma2(acc[jb * 4 + 3], xv[jb], wv3);
        }
        wrow += 32;
        xrow += XT_STRIDE;
        rot = (rot + 1) & 31;
    }

    // ---------- K-quarter reduction via lane-linear smem buffers ----------
    __syncthreads();                               // wT/xT free to reuse
    u64* buf = (u64*)sm;                           // 4 slots * 1024 u64 = 32KB

    if (kq >= 2) {
        int slot = l * 2 + (kq - 2);
        #pragma unroll
        for (int j = 0; j < 32; ++j)
            buf[slot * 1024 + j * 32 + lane] = acc[j];
    }
    __syncthreads();
    if (kq < 2) {
        int slot = l * 2 + kq;
        #pragma unroll
        for (int j = 0; j < 32; ++j)
            acc[j] = add2(acc[j], buf[slot * 1024 + j * 32 + lane]);
        if (kq == 1) {
            #pragma unroll
            for (int j = 0; j < 32; ++j)
                buf[(l * 2 + 1) * 1024 + j * 32 + lane] = acc[j];
        }
    }
    __syncthreads();

    float* gat = (float*)(sm + GAT_OFF);           // [cell*64 + lane*2 + l], 2048 floats
    if (kq == 0) {
        #pragma unroll
        for (int j = 0; j < 32; ++j) {
            u64 s = add2(acc[j], buf[(l * 2 + 1) * 1024 + j * 32 + lane]);
            int m = j & 3;
            int o = og * 4 + m;
            float lo, hi;
            unpackf2(s, lo, hi);
            gat[j * 64 + lane * 2 + l] = lo + hi + bs[l * 32 + o];
        }
    }
    __syncthreads();

    // ---------- epilogue: float2 STG across the 2-w strip ----------
    #pragma unroll
    for (int j = 0; j < 4; ++j) {
        int bo = tid + THREADS * j;                // 0..1023 = b*32 + o
        int b  = bo >> 5;
        int o  = bo & 31;
        int ln   = ((b >> 3) << 3) | (o >> 2);     // writer lane
        int cell = (b & 7) * 4 + (o & 3);          // writer j index
        float2 v = *(const float2*)(gat + cell * 64 + ln * 2);
        *(float2*)(out + (size_t)bo * 4096 + loc0) = v;
    }
}

extern "C" void kernel_launch(void* const* d_in, const int* in_sizes, int n_in,
                              void* d_out, int out_size) {
    const float* x       = (const float*)d_in[0];
    const float* weights = (const float*)d_in[1];
    const float* bias    = (const float*)d_in[2];
    float* out = (float*)d_out;
    (void)in_sizes; (void)n_in; (void)out_size;

    cudaFuncSetAttribute(xonv_kernel, cudaFuncAttributeMaxDynamicSharedMemorySize,
                         SMEM_BYTES);
    xonv_kernel<<<2048, THREADS, SMEM_BYTES>>>(x, weights, bias, out);
}

// round 9
// speedup vs baseline: 1.0438x; 1.0438x over previous
#include <cuda_runtime.h>

typedef unsigned long long u64;

#define THREADS 256
#define NTILES  2048
#define GRID    296

// ---- smem layout (bytes) ----
// weight buffers: per loc 32 o-rows in pairs: off(o) = (o>>1)*1168 + (o&1)*576
#define WPAIR_B  1168
#define WLOC_B   18688                  // 16 pairs * 1168
#define WBUF_B   37376                  // 2 locs per tile
#define XT_OFF_B 74752                  // 2 weight buffers
#define XT_STRIDE 66                    // u64 per pp row: [pp][l*32 + b]
#define XT_B     (72 * XT_STRIDE * 8)   // 38016
#define MB_OFF_B (XT_OFF_B + XT_B)      // 112768
#define SMEM_B   (MB_OFF_B + 32)        // 112800

__device__ __forceinline__ void fma2(u64& d, u64 a, u64 b) {
    asm("fma.rn.f32x2 %0, %1, %2, %0;" : "+l"(d) : "l"(a), "l"(b));
}
__device__ __forceinline__ u64 add2(u64 a, u64 b) {
    u64 r; asm("add.rn.f32x2 %0, %1, %2;" : "=l"(r) : "l"(a), "l"(b)); return r;
}
__device__ __forceinline__ void unpackf2(u64 d, float& lo, float& hi) {
    asm("mov.b64 {%0, %1}, %2;" : "=f"(lo), "=f"(hi) : "l"(d));
}
__device__ __forceinline__ unsigned smem_u32(const void* p) {
    unsigned a;
    asm("{ .reg .u64 t; cvta.to.shared.u64 t, %1; cvt.u32.u64 %0, t; }" : "=r"(a) : "l"(p));
    return a;
}
__device__ __forceinline__ void mb_wait(unsigned mb, int parity) {
    unsigned done;
    do {
        asm volatile("{ .reg .pred p; mbarrier.try_wait.parity.shared.b64 p, [%1], %2; "
                     "selp.b32 %0, 1, 0, p; }" : "=r"(done) : "r"(mb), "r"(parity) : "memory");
    } while (!done);
}

// 64 threads: one 576B bulk copy each (row (l,o)) into the paired layout.
__device__ __forceinline__ void issue_w(const float* __restrict__ weights, unsigned smbase,
                                        int loc0, int buf, unsigned mb, int tid) {
    if (tid < 64) {
        asm volatile("mbarrier.arrive.expect_tx.shared.b64 _, [%0], %1;"
                     :: "r"(mb), "r"(576) : "memory");
        int l = tid >> 5, o = tid & 31;
        const char* src = (const char*)weights + ((size_t)(loc0 + l) * 32 + o) * 576;
        unsigned dst = smbase + buf * WBUF_B + l * WLOC_B + (o >> 1) * WPAIR_B + (o & 1) * 576;
        asm volatile("cp.async.bulk.shared::cta.global.mbarrier::complete_tx::bytes "
                     "[%0], [%1], %2, [%3];"
                     :: "r"(dst), "l"(src), "r"(576), "r"(mb) : "memory");
    }
}

// stage x slab for one tile (2 locs) into xT (p-major, u64-packed p-pairs)
__device__ __forceinline__ void stage_x(const float* __restrict__ x, float* xf,
                                        int h, int w0, int tid) {
    const int lane = tid & 31, wid = tid >> 5;
    const int dr = lane >> 2, c = lane & 3;       // ww = w0 + c - 1
    #pragma unroll 4
    for (int it = 0; it < 24; ++it) {
        int r  = it * 64 + wid * 8 + dr;           // 0..1535 = b*48 + ck
        int b  = r / 48;
        int ck = r - b * 48;
        int ci = ck / 3;
        int kh = ck - ci * 3;
        int hh = h + kh - 1;
        int ww = w0 + c - 1;
        float v = 0.f;
        if ((unsigned)hh < 64u && (unsigned)ww < 64u)
            v = x[(((size_t)b * 16 + ci) * 64 + hh) * 64 + ww];
        int p0 = 3 * ck;
        if (c <= 2) { int p = p0 + c;     xf[((p >> 1) * XT_STRIDE + b) * 2 + (p & 1)] = v; }
        if (c >= 1) { int p = p0 + c - 1; xf[((p >> 1) * XT_STRIDE + 32 + b) * 2 + (p & 1)] = v; }
    }
}

__global__ __launch_bounds__(THREADS, 2) void xonv_kernel(
    const float* __restrict__ x,        // (32, 16, 64, 64)
    const float* __restrict__ weights,  // (64, 64, 32, 16, 3, 3)
    const float* __restrict__ bias,     // (64, 64, 32)
    float* __restrict__ out)            // (32, 32, 64, 64)
{
    extern __shared__ __align__(16) char sm[];
    u64*   xT  = (u64*)(sm + XT_OFF_B);
    float* xf  = (float*)(sm + XT_OFF_B);
    float* gat = (float*)(sm + XT_OFF_B);          // reuses xT between compute & restage
    const unsigned smbase = smem_u32(sm);
    const unsigned mb0 = smbase + MB_OFF_B;
    const unsigned mb1 = smbase + MB_OFF_B + 8;

    const int tid  = threadIdx.x;
    const int lane = tid & 31;
    const int wid  = tid >> 5;

    if (tid == 0) {
        asm volatile("mbarrier.init.shared.b64 [%0], %1;" :: "r"(mb0), "r"(64) : "memory");
        asm volatile("mbarrier.init.shared.b64 [%0], %1;" :: "r"(mb1), "r"(64) : "memory");
    }
    __syncthreads();

    // compute-role constants
    const int l  = wid >> 2;                       // loc within tile
    const int kq = wid & 3;                        // K quarter
    const int bg = lane >> 3;                      // b-octet: b = bg*8 + jb
    const int og = lane & 7;                       // o = og + 8*m

    const int t0 = blockIdx.x;
    {   // prologue: start weights for tile 0, stage its x under the DMA
        int h0 = t0 >> 5, w00 = (t0 & 31) * 2;
        issue_w(weights, smbase, h0 * 64 + w00, 0, mb0, tid);
        stage_x(x, xf, h0, w00, tid);
    }

    int cur = 0, ph0 = 0, ph1 = 0;
    for (int t = t0; t < NTILES; t += GRID, cur ^= 1) {
        const int h    = t >> 5;
        const int w0   = (t & 31) * 2;
        const int loc0 = h * 64 + w0;
        const int tn   = t + GRID;

        // prefetch next tile's weights into the other buffer
        if (tn < NTILES) {
            asm volatile("fence.proxy.async.shared::cta;" ::: "memory");
            issue_w(weights, smbase, (tn >> 5) * 64 + (tn & 31) * 2, cur ^ 1,
                    (cur ^ 1) ? mb1 : mb0, tid);
        }
        // wait for this tile's weights
        if (cur == 0) { mb_wait(mb0, ph0); ph0 ^= 1; }
        else          { mb_wait(mb1, ph1); ph1 ^= 1; }

        // bias prefetch for gather (kq==0 threads only), latency hidden by compute
        float bv0 = 0.f, bv1 = 0.f, bv2 = 0.f, bv3 = 0.f;
        if (kq == 0) {
            const float* bp = bias + (size_t)loc0 * 32 + l * 32 + og;
            bv0 = bp[0]; bv1 = bp[8]; bv2 = bp[16]; bv3 = bp[24];
        }
        __syncthreads();                            // x slab + weights visible

        // ---------------- compute: 8b x 4o per lane, f32x2, K quarter ----------------
        const u64* xrow  = xT + kq * 18 * XT_STRIDE + l * 32 + bg * 8;
        const u64* wbase = (const u64*)(sm + cur * WBUF_B + l * WLOC_B)
                         + (og >> 1) * 146 + (og & 1) * 72 + kq * 18;

        u64 acc[32];
        #pragma unroll
        for (int j = 0; j < 32; ++j) acc[j] = 0ull;

        #pragma unroll 2
        for (int i = 0; i < 18; ++i) {
            u64 wv0 = wbase[0];
            u64 wv1 = wbase[584];
            u64 wv2 = wbase[1168];
            u64 wv3 = wbase[1752];
            ulonglong2 xa = *(const ulonglong2*)(xrow);
            ulonglong2 xb = *(const ulonglong2*)(xrow + 2);
            ulonglong2 xc = *(const ulonglong2*)(xrow + 4);
            ulonglong2 xd = *(const ulonglong2*)(xrow + 6);
            u64 xv[8] = {xa.x, xa.y, xb.x, xb.y, xc.x, xc.y, xd.x, xd.y};
            #pragma unroll
            for (int jb = 0; jb < 8; ++jb) {
                fma2(acc[jb * 4 + 0], xv[jb], wv0);
                fma2(acc[jb * 4 + 1], xv[jb], wv1);
                fma2(acc[jb * 4 + 2], xv[jb], wv2);
                fma2(acc[jb * 4 + 3], xv[jb], wv3);
            }
            wbase += 1;
            xrow  += XT_STRIDE;
        }
        __syncthreads();                            // weights/x consumed

        // ---------------- kq reduction via scratch in the CURRENT weight buffer ------
        u64* buf = (u64*)(sm + cur * WBUF_B);
        if (kq >= 2) {
            int slot = l * 2 + (kq - 2);
            #pragma unroll
            for (int j = 0; j < 32; ++j)
                buf[slot * 1024 + j * 32 + lane] = acc[j];
        }
        __syncthreads();
        if (kq < 2) {
            int slot = l * 2 + kq;
            #pragma unroll
            for (int j = 0; j < 32; ++j)
                acc[j] = add2(acc[j], buf[slot * 1024 + j * 32 + lane]);
            if (kq == 1) {
                #pragma unroll
                for (int j = 0; j < 32; ++j)
                    buf[(l * 2 + 1) * 1024 + j * 32 + lane] = acc[j];
            }
        }
        __syncthreads();
        if (kq == 0) {                              // final add + bias, into gather buf
            #pragma unroll
            for (int j = 0; j < 32; ++j) {
                u64 s = add2(acc[j], buf[(l * 2 + 1) * 1024 + j * 32 + lane]);
                float lo, hi;
                unpackf2(s, lo, hi);
                int m = j & 3;
                float bv = (m == 0) ? bv0 : (m == 1) ? bv1 : (m == 2) ? bv2 : bv3;
                gat[j * 64 + lane * 2 + l] = lo + hi + bv;
            }
        }
        __syncthreads();

        // ---------------- epilogue: float2 STG across the 2-w strip ------------------
        #pragma unroll
        for (int k = 0; k < 4; ++k) {
            int bo = tid + THREADS * k;             // 0..1023 = b*32 + o
            int b  = bo >> 5;
            int o  = bo & 31;
            int ln   = ((b >> 3) << 3) | (o & 7);
            int cell = (b & 7) * 4 + (o >> 3);
            float2 v = *(const float2*)(gat + cell * 64 + ln * 2);
            *(float2*)(out + (size_t)bo * 4096 + loc0) = v;
        }
        __syncthreads();                            // gather consumed

        // restage x for the next tile (overwrites gather region + x slab)
        if (tn < NTILES)
            stage_x(x, xf, tn >> 5, (tn & 31) * 2, tid);
    }
}

extern "C" void kernel_launch(void* const* d_in, const int* in_sizes, int n_in,
                              void* d_out, int out_size) {
    const float* x       = (const float*)d_in[0];
    const float* weights = (const float*)d_in[1];
    const float* bias    = (const float*)d_in[2];
    float* out = (float*)d_out;
    (void)in_sizes; (void)n_in; (void)out_size;

    cudaFuncSetAttribute(xonv_kernel, cudaFuncAttributeMaxDynamicSharedMemorySize, SMEM_B);
    xonv_kernel<<<GRID, THREADS, SMEM_B>>>(x, weights, bias, out);
}

// round 10
// speedup vs baseline: 1.2966x; 1.2422x over previous
#include <cuda_runtime.h>

typedef unsigned long long u64;

#define THREADS 256
#define GRID    2048

// ---- smem layout (bytes) ----
// weights: per loc 16 o-pairs, pair row = 1168B (2 x 576 + 16 pad); u64 idx:
//   widx(l,o,pp) = l*2336 + (o>>1)*146 + (o&1)*72 + pp
#define WBUF_B   37376
#define XT_OFF   37376                 // xT: 72 rows x 64 u64, chunk-XOR swizzled
#define XT_B     36864
#define MB_OFF   (XT_OFF + XT_B)       // 74240
#define SMEM_B   (MB_OFF + 16)         // 74256 -> 3 CTAs/SM
// reduction scratch + gather overlay the weight buffer after compute
#define GAT_OFF  16384                 // floats, within [0, WBUF_B)

__device__ __forceinline__ void fma2(u64& d, u64 a, u64 b) {
    asm("fma.rn.f32x2 %0, %1, %2, %0;" : "+l"(d) : "l"(a), "l"(b));
}
__device__ __forceinline__ u64 add2(u64 a, u64 b) {
    u64 r; asm("add.rn.f32x2 %0, %1, %2;" : "=l"(r) : "l"(a), "l"(b)); return r;
}
__device__ __forceinline__ void unpackf2(u64 d, float& lo, float& hi) {
    asm("mov.b64 {%0, %1}, %2;" : "=f"(lo), "=f"(hi) : "l"(d));
}
__device__ __forceinline__ unsigned smem_u32(const void* p) {
    unsigned a;
    asm("{ .reg .u64 t; cvta.to.shared.u64 t, %1; cvt.u32.u64 %0, t; }" : "=r"(a) : "l"(p));
    return a;
}

__global__ __launch_bounds__(THREADS, 3) void xonv_kernel(
    const float* __restrict__ x,        // (32, 16, 64, 64)
    const float* __restrict__ weights,  // (64, 64, 32, 16, 3, 3)
    const float* __restrict__ bias,     // (64, 64, 32)
    float* __restrict__ out)            // (32, 32, 64, 64)
{
    extern __shared__ __align__(16) char sm[];
    u64*   wsm = (u64*)sm;
    u64*   xt  = (u64*)(sm + XT_OFF);
    float* xf  = (float*)(sm + XT_OFF);
    const unsigned smbase = smem_u32(sm);
    const unsigned mb = smbase + MB_OFF;

    const int tid  = threadIdx.x;
    const int lane = tid & 31;
    const int wid  = tid >> 5;
    const int t    = blockIdx.x;
    const int h    = t >> 5;
    const int w0   = (t & 31) * 2;
    const int loc0 = h * 64 + w0;

    // ---------------- weights via bulk DMA into paired layout ----------------
    if (tid == 0)
        asm volatile("mbarrier.init.shared.b64 [%0], %1;" :: "r"(mb), "r"(64) : "memory");
    __syncthreads();
    if (tid < 64) {                            // row = (l, o)
        asm volatile("mbarrier.arrive.expect_tx.shared.b64 _, [%0], %1;"
                     :: "r"(mb), "r"(576) : "memory");
        int l = tid >> 5, o = tid & 31;
        const char* src = (const char*)weights + ((size_t)(loc0 + l) * 32 + o) * 576;
        unsigned dst = smbase + l * 18688 + (o >> 1) * 1168 + (o & 1) * 576;
        asm volatile("cp.async.bulk.shared::cta.global.mbarrier::complete_tx::bytes "
                     "[%0], [%1], %2, [%3];"
                     :: "r"(dst), "l"(src), "r"(576), "r"(mb) : "memory");
    }

    // ---------------- stage x (overlaps DMA): swizzled p-major layout ----------------
    // float idx = pp*128 + phys*4 + (b&1)*2 + (p&1), phys = (l*16 + (b>>1)) ^ (pp & 15)
    {
        const int dr = lane >> 2, c = lane & 3;        // ww = w0 + c - 1
        #pragma unroll 4
        for (int it = 0; it < 24; ++it) {
            int r  = it * 64 + wid * 8 + dr;           // 0..1535 = b*48 + ck
            int b  = r / 48;
            int ck = r - b * 48;
            int ci = ck / 3;
            int kh = ck - ci * 3;
            int hh = h + kh - 1;
            int ww = w0 + c - 1;
            float v = 0.f;
            if ((unsigned)hh < 64u && (unsigned)ww < 64u)
                v = x[(((size_t)b * 16 + ci) * 64 + hh) * 64 + ww];
            int bh = b >> 1, bl = (b & 1) * 2;
            if (c <= 2) {                              // l = 0, kw = c
                int p = 3 * ck + c, pp = p >> 1;
                xf[pp * 128 + ((bh) ^ (pp & 15)) * 4 + bl + (p & 1)] = v;
            }
            if (c >= 1) {                              // l = 1, kw = c - 1
                int p = 3 * ck + c - 1, pp = p >> 1;
                xf[pp * 128 + ((16 + bh) ^ (pp & 15)) * 4 + bl + (p & 1)] = v;
            }
        }
    }

    // ---------------- roles ----------------
    const int l  = wid >> 2;                   // loc
    const int kh = (wid >> 1) & 1;             // K half
    const int oh = wid & 1;                    // o half
    const int bg = lane >> 2;                  // b = bg*4 + jb
    const int og = lane & 3;                   // o = oh*16 + 4m + og

    // bias prefetch (kh==0 warps produce outputs)
    float bv0 = 0.f, bv1 = 0.f, bv2 = 0.f, bv3 = 0.f;
    if (kh == 0) {
        const float* bp = bias + (size_t)(loc0 + l) * 32 + oh * 16 + og;
        bv0 = bp[0]; bv1 = bp[4]; bv2 = bp[8]; bv3 = bp[12];
    }

    // wait weights
    {
        unsigned done;
        do {
            asm volatile("{ .reg .pred p; mbarrier.try_wait.parity.shared.b64 p, [%1], %2; "
                         "selp.b32 %0, 1, 0, p; }" : "=r"(done) : "r"(mb), "r"(0) : "memory");
        } while (!done);
    }
    __syncthreads();                           // x + weights visible

    // ---------------- compute: 36 pp-steps, tile 4b x 4o ----------------
    const u64* wb = wsm + l * 2336 + (oh * 8 + (og >> 1)) * 146 + (og & 1) * 72 + kh * 36;
    const int c0 = l * 16 + bg * 2;            // chunk pair for this lane's 4 b's

    u64 acc[16];                               // [jb*4 + m]
    #pragma unroll
    for (int j = 0; j < 16; ++j) acc[j] = 0ull;

    #pragma unroll 4
    for (int i = 0; i < 36; ++i) {
        int ppg = kh * 36 + i;
        int rot = ppg & 15;
        const u64* xr = xt + ppg * 64;
        ulonglong2 xa = *(const ulonglong2*)(xr + (((c0)     ^ rot) << 1));
        ulonglong2 xb = *(const ulonglong2*)(xr + (((c0 + 1) ^ rot) << 1));
        u64 wv0 = wb[0];
        u64 wv1 = wb[292];
        u64 wv2 = wb[584];
        u64 wv3 = wb[876];
        u64 xv0 = xa.x, xv1 = xa.y, xv2 = xb.x, xv3 = xb.y;
        fma2(acc[0],  xv0, wv0); fma2(acc[1],  xv0, wv1);
        fma2(acc[2],  xv0, wv2); fma2(acc[3],  xv0, wv3);
        fma2(acc[4],  xv1, wv0); fma2(acc[5],  xv1, wv1);
        fma2(acc[6],  xv1, wv2); fma2(acc[7],  xv1, wv3);
        fma2(acc[8],  xv2, wv0); fma2(acc[9],  xv2, wv1);
        fma2(acc[10], xv2, wv2); fma2(acc[11], xv2, wv3);
        fma2(acc[12], xv3, wv0); fma2(acc[13], xv3, wv1);
        fma2(acc[14], xv3, wv2); fma2(acc[15], xv3, wv3);
        wb += 1;
    }
    __syncthreads();                           // weights consumed; reuse wsm

    // ---------------- K-half reduction ----------------
    u64* slots = wsm;                          // 4 slots x 512 u64 = 16KB
    const int slot = l * 2 + oh;
    if (kh == 1) {
        #pragma unroll
        for (int j = 0; j < 16; ++j)
            slots[slot * 512 + j * 32 + lane] = acc[j];
    }
    __syncthreads();

    float* gat = (float*)(sm + GAT_OFF);       // word = og*2 + bg*8 + cell*66 (+l)
    if (kh == 0) {
        #pragma unroll
        for (int j = 0; j < 16; ++j) {
            u64 s = add2(acc[j], slots[slot * 512 + j * 32 + lane]);
            float lo, hi;
            unpackf2(s, lo, hi);
            int jb = j >> 2, m = j & 3;
            float bv = (m == 0) ? bv0 : (m == 1) ? bv1 : (m == 2) ? bv2 : bv3;
            int cell = m + jb * 4 + oh * 16;
            gat[og * 2 + bg * 8 + cell * 66 + l] = lo + hi + bv;
        }
    }
    __syncthreads();

    // ---------------- epilogue: float2 STG over the 2-w strip ----------------
    #pragma unroll
    for (int k = 0; k < 4; ++k) {
        int bo = tid + THREADS * k;            // 0..1023 = b*32 + o
        int rog = bo & 3;
        int rm  = (bo >> 2) & 3;
        int roh = (bo >> 4) & 1;
        int rjb = (bo >> 5) & 3;
        int rbg = (bo >> 7) & 7;
        int cell = rm + rjb * 4 + roh * 16;
        float2 v = *(const float2*)(gat + rog * 2 + rbg * 8 + cell * 66);
        *(float2*)(out + (size_t)bo * 4096 + loc0) = v;
    }
}

extern "C" void kernel_launch(void* const* d_in, const int* in_sizes, int n_in,
                              void* d_out, int out_size) {
    const float* x       = (const float*)d_in[0];
    const float* weights = (const float*)d_in[1];
    const float* bias    = (const float*)d_in[2];
    float* out = (float*)d_out;
    (void)in_sizes; (void)n_in; (void)out_size;

    cudaFuncSetAttribute(xonv_kernel, cudaFuncAttributeMaxDynamicSharedMemorySize, SMEM_B);
    xonv_kernel<<<GRID, THREADS, SMEM_B>>>(x, weights, bias, out);
}

// round 11
// speedup vs baseline: 1.3291x; 1.0250x over previous
#include <cuda_runtime.h>

typedef unsigned long long u64;

#define THREADS 256
#define GRID    2048

// ---- smem layout (bytes) ----
// weights: per loc 16 o-pairs, pair row = 1168B (2 x 576 + 16 pad); u64 idx:
//   widx(l,o,pp) = l*2336 + (o>>1)*146 + (o&1)*72 + pp
#define WBUF_B   37376
#define XT_OFF   37376                 // xT: 144 rows (pp*2+l) x 34 u64, bit-interleaved b
#define XT_B     39168
#define MB_OFF   (XT_OFF + XT_B)       // 76544
#define SMEM_B   (MB_OFF + 16)         // 76560
#define GAT_OFF  16384                 // gather floats, inside weight buffer after compute

__device__ __forceinline__ void fma2(u64& d, u64 a, u64 b) {
    asm("fma.rn.f32x2 %0, %1, %2, %0;" : "+l"(d) : "l"(a), "l"(b));
}
__device__ __forceinline__ u64 add2(u64 a, u64 b) {
    u64 r; asm("add.rn.f32x2 %0, %1, %2;" : "=l"(r) : "l"(a), "l"(b)); return r;
}
__device__ __forceinline__ void unpackf2(u64 d, float& lo, float& hi) {
    asm("mov.b64 {%0, %1}, %2;" : "=f"(lo), "=f"(hi) : "l"(d));
}
__device__ __forceinline__ unsigned smem_u32(const void* p) {
    unsigned a;
    asm("{ .reg .u64 t; cvta.to.shared.u64 t, %1; cvt.u32.u64 %0, t; }" : "=r"(a) : "l"(p));
    return a;
}

__global__ __launch_bounds__(THREADS, 3) void xonv_kernel(
    const float* __restrict__ x,        // (32, 16, 64, 64)
    const float* __restrict__ weights,  // (64, 64, 32, 16, 3, 3)
    const float* __restrict__ bias,     // (64, 64, 32)
    float* __restrict__ out)            // (32, 32, 64, 64)
{
    extern __shared__ __align__(16) char sm[];
    u64*   wsm = (u64*)sm;
    u64*   xt  = (u64*)(sm + XT_OFF);
    float* xf  = (float*)(sm + XT_OFF);
    const unsigned smbase = smem_u32(sm);
    const unsigned mb = smbase + MB_OFF;

    const int tid  = threadIdx.x;
    const int lane = tid & 31;
    const int wid  = tid >> 5;
    const int t    = blockIdx.x;
    const int h    = t >> 5;
    const int w0   = (t & 31) * 2;
    const int loc0 = h * 64 + w0;

    // ---------------- weights via bulk DMA into paired layout ----------------
    if (tid == 0)
        asm volatile("mbarrier.init.shared.b64 [%0], %1;" :: "r"(mb), "r"(64) : "memory");
    __syncthreads();
    if (tid < 64) {                            // row = (l, o)
        asm volatile("mbarrier.arrive.expect_tx.shared.b64 _, [%0], %1;"
                     :: "r"(mb), "r"(576) : "memory");
        int l = tid >> 5, o = tid & 31;
        const char* src = (const char*)weights + ((size_t)(loc0 + l) * 32 + o) * 576;
        unsigned dst = smbase + l * 18688 + (o >> 1) * 1168 + (o & 1) * 576;
        asm volatile("cp.async.bulk.shared::cta.global.mbarrier::complete_tx::bytes "
                     "[%0], [%1], %2, [%3];"
                     :: "r"(dst), "l"(src), "r"(576), "r"(mb) : "memory");
    }

    // ---------------- stage x (overlaps DMA): bit-interleaved p-major layout --------
    // float idx = (pp*2+l)*68 + ((b>>2) + ((b>>1)&1)*8)*4 + (b&1)*2 + (p&1)
    {
        const int dr = lane >> 2, c = lane & 3;        // ww = w0 + c - 1
        #pragma unroll 4
        for (int it = 0; it < 24; ++it) {
            int r  = it * 64 + wid * 8 + dr;           // 0..1535 = b*48 + ck
            int b  = r / 48;
            int ck = r - b * 48;
            int ci = ck / 3;
            int kh = ck - ci * 3;
            int hh = h + kh - 1;
            int ww = w0 + c - 1;
            float v = 0.f;
            if ((unsigned)hh < 64u && (unsigned)ww < 64u)
                v = x[(((size_t)b * 16 + ci) * 64 + hh) * 64 + ww];
            int bo = ((b >> 2) + ((b >> 1) & 1) * 8) * 4 + (b & 1) * 2;
            if (c <= 2) {                              // l = 0, kw = c
                int p = 3 * ck + c;
                xf[(p >> 1) * 136 + bo + (p & 1)] = v;
            }
            if (c >= 1) {                              // l = 1, kw = c - 1
                int p = 3 * ck + c - 1;
                xf[(p >> 1) * 136 + 68 + bo + (p & 1)] = v;
            }
        }
    }

    // ---------------- roles ----------------
    const int l  = wid >> 2;                   // loc
    const int kh = (wid >> 1) & 1;             // K half
    const int oh = wid & 1;                    // o half
    const int bg = lane >> 2;                  // b = bg*4 + jb
    const int og = lane & 3;                   // o = oh*16 + m*4 + og

    // bias prefetch (kh==0 warps produce outputs)
    float bv0 = 0.f, bv1 = 0.f, bv2 = 0.f, bv3 = 0.f;
    if (kh == 0) {
        const float* bp = bias + (size_t)(loc0 + l) * 32 + oh * 16 + og;
        bv0 = bp[0]; bv1 = bp[4]; bv2 = bp[8]; bv3 = bp[12];
    }

    // wait weights
    {
        unsigned done;
        do {
            asm volatile("{ .reg .pred p; mbarrier.try_wait.parity.shared.b64 p, [%1], %2; "
                         "selp.b32 %0, 1, 0, p; }" : "=r"(done) : "r"(mb), "r"(0) : "memory");
        } while (!done);
    }
    __syncthreads();                           // x + weights visible

    // ---------------- compute: 18 double-pp steps, tile 4b x 4o ----------------
    const u64* xrow = xt + (size_t)(kh * 36 * 2 + l) * 34 + bg * 2;
    const u64* wb   = wsm + l * 2336 + (oh * 8 + (og >> 1)) * 146 + (og & 1) * 72 + kh * 36;

    u64 acc[16];                               // [jb*4 + m]
    #pragma unroll
    for (int j = 0; j < 16; ++j) acc[j] = 0ull;

    #pragma unroll 2
    for (int i = 0; i < 18; ++i) {
        // w pairs: .x = pp0, .y = pp1, one LDS.128 per m (conflict-free phases)
        ulonglong2 wv0 = *(const ulonglong2*)(wb);
        ulonglong2 wv1 = *(const ulonglong2*)(wb + 292);
        ulonglong2 wv2 = *(const ulonglong2*)(wb + 584);
        ulonglong2 wv3 = *(const ulonglong2*)(wb + 876);
        // x: unit phases bg and bg+8 -> conflict-free LDS.128
        ulonglong2 xa0 = *(const ulonglong2*)(xrow);        // pp0: b = 4bg, 4bg+1
        ulonglong2 xb0 = *(const ulonglong2*)(xrow + 16);   // pp0: b = 4bg+2, 4bg+3
        ulonglong2 xa1 = *(const ulonglong2*)(xrow + 68);   // pp1
        ulonglong2 xb1 = *(const ulonglong2*)(xrow + 84);

        fma2(acc[0],  xa0.x, wv0.x); fma2(acc[0],  xa1.x, wv0.y);
        fma2(acc[1],  xa0.x, wv1.x); fma2(acc[1],  xa1.x, wv1.y);
        fma2(acc[2],  xa0.x, wv2.x); fma2(acc[2],  xa1.x, wv2.y);
        fma2(acc[3],  xa0.x, wv3.x); fma2(acc[3],  xa1.x, wv3.y);
        fma2(acc[4],  xa0.y, wv0.x); fma2(acc[4],  xa1.y, wv0.y);
        fma2(acc[5],  xa0.y, wv1.x); fma2(acc[5],  xa1.y, wv1.y);
        fma2(acc[6],  xa0.y, wv2.x); fma2(acc[6],  xa1.y, wv2.y);
        fma2(acc[7],  xa0.y, wv3.x); fma2(acc[7],  xa1.y, wv3.y);
        fma2(acc[8],  xb0.x, wv0.x); fma2(acc[8],  xb1.x, wv0.y);
        fma2(acc[9],  xb0.x, wv1.x); fma2(acc[9],  xb1.x, wv1.y);
        fma2(acc[10], xb0.x, wv2.x); fma2(acc[10], xb1.x, wv2.y);
        fma2(acc[11], xb0.x, wv3.x); fma2(acc[11], xb1.x, wv3.y);
        fma2(acc[12], xb0.y, wv0.x); fma2(acc[12], xb1.y, wv0.y);
        fma2(acc[13], xb0.y, wv1.x); fma2(acc[13], xb1.y, wv1.y);
        fma2(acc[14], xb0.y, wv2.x); fma2(acc[14], xb1.y, wv2.y);
        fma2(acc[15], xb0.y, wv3.x); fma2(acc[15], xb1.y, wv3.y);

        xrow += 136;
        wb   += 2;
    }
    __syncthreads();                           // weights consumed; reuse wsm

    // ---------------- K-half reduction ----------------
    u64* slots = wsm;                          // 4 slots x 512 u64 = 16KB
    const int slot = l * 2 + oh;
    if (kh == 1) {
        #pragma unroll
        for (int j = 0; j < 16; ++j)
            slots[slot * 512 + j * 32 + lane] = acc[j];
    }
    __syncthreads();

    float* gat = (float*)(sm + GAT_OFF);       // word = og*2 + bg*8 + cell*66 (+l)
    if (kh == 0) {
        #pragma unroll
        for (int j = 0; j < 16; ++j) {
            u64 s = add2(acc[j], slots[slot * 512 + j * 32 + lane]);
            float lo, hi;
            unpackf2(s, lo, hi);
            int jb = j >> 2, m = j & 3;
            float bv = (m == 0) ? bv0 : (m == 1) ? bv1 : (m == 2) ? bv2 : bv3;
            int cell = m + jb * 4 + oh * 16;
            gat[og * 2 + bg * 8 + cell * 66 + l] = lo + hi + bv;
        }
    }
    __syncthreads();

    // ---------------- epilogue: float2 STG over the 2-w strip ----------------
    #pragma unroll
    for (int k = 0; k < 4; ++k) {
        int bo = tid + THREADS * k;            // 0..1023 = b*32 + o
        int rog = bo & 3;
        int rm  = (bo >> 2) & 3;
        int roh = (bo >> 4) & 1;
        int rjb = (bo >> 5) & 3;
        int rbg = (bo >> 7) & 7;
        int cell = rm + rjb * 4 + roh * 16;
        float2 v = *(const float2*)(gat + rog * 2 + rbg * 8 + cell * 66);
        *(float2*)(out + (size_t)bo * 4096 + loc0) = v;
    }
}

extern "C" void kernel_launch(void* const* d_in, const int* in_sizes, int n_in,
                              void* d_out, int out_size) {
    const float* x       = (const float*)d_in[0];
    const float* weights = (const float*)d_in[1];
    const float* bias    = (const float*)d_in[2];
    float* out = (float*)d_out;
    (void)in_sizes; (void)n_in; (void)out_size;

    cudaFuncSetAttribute(xonv_kernel, cudaFuncAttributeMaxDynamicSharedMemorySize, SMEM_B);
    xonv_kernel<<<GRID, THREADS, SMEM_B>>>(x, weights, bias, out);
}

// round 12
// speedup vs baseline: 1.6117x; 1.2126x over previous
#include <cuda_runtime.h>

typedef unsigned long long u64;

#define THREADS 256
#define GRID    4096

#define W_B     18688
#define XT_OFF  18688
#define XT_B    19584
#define MB_OFF  (XT_OFF + XT_B)
#define SMEM_B  (MB_OFF + 16)

__device__ __forceinline__ void fma2(u64& d, u64 a, u64 b) {
    asm("fma.rn.f32x2 %0, %1, %2, %0;" : "+l"(d) : "l"(a), "l"(b));
}
__device__ __forceinline__ u64 add2(u64 a, u64 b) {
    u64 r; asm("add.rn.f32x2 %0, %1, %2;" : "=l"(r) : "l"(a), "l"(b)); return r;
}
__device__ __forceinline__ void unpackf2(u64 d, float& lo, float& hi) {
    asm("mov.b64 {%0, %1}, %2;" : "=f"(lo), "=f"(hi) : "l"(d));
}
__device__ __forceinline__ unsigned smem_u32(const void* p) {
    unsigned a;
    asm("{ .reg .u64 t; cvta.to.shared.u64 t, %1; cvt.u32.u64 %0, t; }" : "=r"(a) : "l"(p));
    return a;
}

__global__ __launch_bounds__(THREADS, 4) void xonv_kernel(
    const float* __restrict__ x,        // (32, 16, 64, 64)
    const float* __restrict__ weights,  // (64, 64, 32, 16, 3, 3)
    const float* __restrict__ bias,     // (64, 64, 32)
    float* __restrict__ out)            // (32, 32, 64, 64)
{
    extern __shared__ __align__(16) char sm[];
    u64*   wsm = (u64*)sm;
    u64*   xt  = (u64*)(sm + XT_OFF);
    float* xf  = (float*)(sm + XT_OFF);
    const unsigned smbase = smem_u32(sm);
    const unsigned mb = smbase + MB_OFF;

    const int tid  = threadIdx.x;
    const int lane = tid & 31;
    const int wid  = tid >> 5;
    const int loc  = blockIdx.x;
    const int h    = loc >> 6;
    const int w0   = loc & 63;

    if (tid == 0)
        asm volatile("mbarrier.init.shared.b64 [%0], %1;" :: "r"(mb), "r"(32) : "memory");
    __syncthreads();
    if (tid < 32) {
        asm volatile("mbarrier.arrive.expect_tx.shared.b64 _, [%0], %1;"
                     :: "r"(mb), "r"(576) : "memory");
        const char* src = (const char*)weights + ((size_t)loc * 32 + tid) * 576;
        unsigned dst = smbase + (tid >> 1) * 1168 + (tid & 1) * 576;
        asm volatile("cp.async.bulk.shared::cta.global.mbarrier::complete_tx::bytes "
                     "[%0], [%1], %2, [%3];"
                     :: "r"(dst), "l"(src), "r"(576), "r"(mb) : "memory");
    }

    {   // stage x, division-free: idx = (p>>1)*68 + b*2 + (p&1), p = 3*ck + c
        const int dr = lane >> 2;
        const int c  = lane & 3;
        if (c < 3) {
            const int ww = w0 + c - 1;
            const bool wok = (unsigned)ww < 64u;
            #pragma unroll
            for (int itb = 0; itb < 4; ++itb) {
                const int b = itb * 8 + wid;
                const float* xb = x + (size_t)b * 65536;   // 16*64*64
                #pragma unroll
                for (int itc = 0; itc < 6; ++itc) {
                    int ck = itc * 8 + dr;
                    int ci = (ck * 683) >> 11;             // ck/3
                    int kh = ck - ci * 3;
                    int hh = h + kh - 1;
                    float v = 0.f;
                    if ((unsigned)hh < 64u && wok)
                        v = xb[ci * 4096 + hh * 64 + ww];
                    int p = 3 * ck + c;
                    xf[(p >> 1) * 68 + b * 2 + (p & 1)] = v;
                }
            }
        }
    }

    const int kq = wid >> 1;
    const int oh = wid & 1;
    const int bg = lane >> 2;
    const int og = lane & 3;

    float bv0 = 0.f, bv1 = 0.f, bv2 = 0.f, bv3 = 0.f;
    if (kq == 0) {
        const float* bp = bias + (size_t)loc * 32 + oh * 16 + og;
        bv0 = bp[0]; bv1 = bp[4]; bv2 = bp[8]; bv3 = bp[12];
    }

    __syncthreads();
    {
        unsigned done;
        do {
            asm volatile("{ .reg .pred p; mbarrier.try_wait.parity.shared.b64 p, [%1], %2; "
                         "selp.b32 %0, 1, 0, p; }" : "=r"(done) : "r"(mb), "r"(0) : "memory");
        } while (!done);
    }

    const u64* xrow = xt + kq * 18 * 34 + bg * 4;
    const u64* wb   = wsm + (oh * 8 + (og >> 1)) * 146 + (og & 1) * 72 + kq * 18;

    u64 acc[16];
    #pragma unroll
    for (int j = 0; j < 16; ++j) acc[j] = 0ull;

    #pragma unroll 3
    for (int i = 0; i < 18; ++i) {
        ulonglong2 xa = *(const ulonglong2*)(xrow);
        ulonglong2 xc = *(const ulonglong2*)(xrow + 2);
        u64 wv0 = wb[0];
        u64 wv1 = wb[292];
        u64 wv2 = wb[584];
        u64 wv3 = wb[876];
        fma2(acc[0],  xa.x, wv0); fma2(acc[1],  xa.x, wv1);
        fma2(acc[2],  xa.x, wv2); fma2(acc[3],  xa.x, wv3);
        fma2(acc[4],  xa.y, wv0); fma2(acc[5],  xa.y, wv1);
        fma2(acc[6],  xa.y, wv2); fma2(acc[7],  xa.y, wv3);
        fma2(acc[8],  xc.x, wv0); fma2(acc[9],  xc.x, wv1);
        fma2(acc[10], xc.x, wv2); fma2(acc[11], xc.x, wv3);
        fma2(acc[12], xc.y, wv0); fma2(acc[13], xc.y, wv1);
        fma2(acc[14], xc.y, wv2); fma2(acc[15], xc.y, wv3);
        xrow += 34;
        wb   += 1;
    }
    __syncthreads();

    u64* slots = wsm;
    if (kq >= 2) {
        int slot = oh * 2 + (kq & 1);
        #pragma unroll
        for (int j = 0; j < 16; ++j)
            slots[slot * 512 + j * 32 + lane] = acc[j];
    }
    __syncthreads();
    if (kq < 2) {
        int slot = oh * 2 + kq;
        #pragma unroll
        for (int j = 0; j < 16; ++j)
            acc[j] = add2(acc[j], slots[slot * 512 + j * 32 + lane]);
        if (kq == 1) {
            #pragma unroll
            for (int j = 0; j < 16; ++j)
                slots[(oh * 2 + 1) * 512 + j * 32 + lane] = acc[j];
        }
    }
    __syncthreads();

    if (kq == 0) {
        #pragma unroll
        for (int j = 0; j < 16; ++j) {
            u64 s = add2(acc[j], slots[(oh * 2 + 1) * 512 + j * 32 + lane]);
            float lo, hi;
            unpackf2(s, lo, hi);
            int jb = j >> 2, m = j & 3;
            int b = bg * 4 + jb;
            int o = oh * 16 + m * 4 + og;
            float bvm = (m == 0) ? bv0 : (m == 1) ? bv1 : (m == 2) ? bv2 : bv3;
            out[(size_t)(b * 32 + o) * 4096 + loc] = lo + hi + bvm;
        }
    }
}

extern "C" void kernel_launch(void* const* d_in, const int* in_sizes, int n_in,
                              void* d_out, int out_size) {
    const float* x       = (const float*)d_in[0];
    const float* weights = (const float*)d_in[1];
    const float* bias    = (const float*)d_in[2];
    float* out = (float*)d_out;
    (void)in_sizes; (void)n_in; (void)out_size;

    cudaFuncSetAttribute(xonv_kernel, cudaFuncAttributeMaxDynamicSharedMemorySize, SMEM_B);
    xonv_kernel<<<GRID, THREADS, SMEM_B>>>(x, weights, bias, out);
}

// round 13
// speedup vs baseline: 1.7810x; 1.1050x over previous
#include <cuda_runtime.h>

typedef unsigned long long u64;

#define THREADS 256
#define GRID    2048

// ---- smem (bytes) ----
// w buf: paired o-rows, float idx w(o,p) = (o>>1)*292 + (o&1)*144 + p
#define WBUF_B   18688
#define SLAB_OFF 18688          // slab: 192 rows (ck*4+col) x 36 floats (32 b + 4 pad)
#define SLAB_B   27648
#define MB_OFF   (SLAB_OFF + SLAB_B)    // 46336
#define SMEM_B   (MB_OFF + 16)          // 46352 -> 4 CTAs/SM

__device__ __forceinline__ void fma2(u64& d, u64 a, u64 b) {
    asm("fma.rn.f32x2 %0, %1, %2, %0;" : "+l"(d) : "l"(a), "l"(b));
}
__device__ __forceinline__ u64 add2(u64 a, u64 b) {
    u64 r; asm("add.rn.f32x2 %0, %1, %2;" : "=l"(r) : "l"(a), "l"(b)); return r;
}
__device__ __forceinline__ u64 pack2(float v) {
    u64 r; asm("mov.b64 %0, {%1, %1};" : "=l"(r) : "f"(v)); return r;
}
__device__ __forceinline__ void unpackf2(u64 d, float& lo, float& hi) {
    asm("mov.b64 {%0, %1}, %2;" : "=f"(lo), "=f"(hi) : "l"(d));
}
__device__ __forceinline__ unsigned smem_u32(const void* p) {
    unsigned a;
    asm("{ .reg .u64 t; cvta.to.shared.u64 t, %1; cvt.u32.u64 %0, t; }" : "=r"(a) : "l"(p));
    return a;
}

__global__ __launch_bounds__(THREADS, 4) void xonv_kernel(
    const float* __restrict__ x,        // (32, 16, 64, 64)
    const float* __restrict__ weights,  // (64, 64, 32, 16, 3, 3)
    const float* __restrict__ bias,     // (64, 64, 32)
    float* __restrict__ out)            // (32, 32, 64, 64)
{
    extern __shared__ __align__(16) char sm[];
    float* wsf   = (float*)sm;
    float* slabf = (float*)(sm + SLAB_OFF);
    const unsigned smbase = smem_u32(sm);
    const unsigned mb = smbase + MB_OFF;

    const int tid  = threadIdx.x;
    const int lane = tid & 31;
    const int wid  = tid >> 5;
    const int h    = blockIdx.x >> 5;
    const int w0   = (blockIdx.x & 31) * 2;
    const int loc0 = h * 64 + w0;

    if (tid == 0)
        asm volatile("mbarrier.init.shared.b64 [%0], %1;" :: "r"(mb), "r"(32) : "memory");
    __syncthreads();

    // -------- DMA weights for loc0 (32 x 576B into paired rows) --------
    if (tid < 32) {
        asm volatile("mbarrier.arrive.expect_tx.shared.b64 _, [%0], %1;"
                     :: "r"(mb), "r"(576) : "memory");
        const char* src = (const char*)weights + ((size_t)loc0 * 32 + tid) * 576;
        unsigned dst = smbase + (tid >> 1) * 1168 + (tid & 1) * 576;
        asm volatile("cp.async.bulk.shared::cta.global.mbarrier::complete_tx::bytes "
                     "[%0], [%1], %2, [%3];"
                     :: "r"(dst), "l"(src), "r"(576), "r"(mb) : "memory");
    }

    // -------- stage shared x slab: rows (ck,col 0..3), cols = w0-1..w0+2 --------
    {
        const int dr = lane >> 2;              // 0..7
        const int c  = lane & 3;               // col
        const int ww = w0 + c - 1;
        const bool wok = (unsigned)ww < 64u;
        #pragma unroll
        for (int itb = 0; itb < 4; ++itb) {
            const int b = itb * 8 + wid;
            const float* xb = x + (size_t)b * 65536;
            #pragma unroll
            for (int itc = 0; itc < 6; ++itc) {
                int ck = itc * 8 + dr;
                int ci = (ck * 683) >> 11;     // ck/3
                int kh = ck - ci * 3;
                int hh = h + kh - 1;
                float v = 0.f;
                if ((unsigned)hh < 64u && wok)
                    v = xb[ci * 4096 + hh * 64 + ww];
                slabf[(ck * 4 + c) * 36 + b] = v;
            }
        }
    }
    __syncthreads();                           // slab ready

    const int kq = wid >> 1;                   // K quarter
    const int oh = wid & 1;                    // o half
    const int bg = lane >> 2;                  // b = bg*4 + ...
    const int og = lane & 3;                   // o = oh*16 + m*4 + og

    const float* wpf = wsf + (oh * 8 + (og >> 1)) * 292 + (og & 1) * 144 + kq * 36;

    int parity = 0;
    #pragma unroll
    for (int l = 0; l < 2; ++l) {
        const int loc = loc0 + l;

        // bias prefetch (kq0 produces outputs)
        float bv0 = 0.f, bv1 = 0.f, bv2 = 0.f, bv3 = 0.f;
        if (kq == 0) {
            const float* bp = bias + (size_t)loc * 32 + oh * 16 + og;
            bv0 = bp[0]; bv1 = bp[4]; bv2 = bp[8]; bv3 = bp[12];
        }

        // wait for this loc's weights
        {
            unsigned done;
            do {
                asm volatile("{ .reg .pred p; mbarrier.try_wait.parity.shared.b64 p, [%1], %2; "
                             "selp.b32 %0, 1, 0, p; }"
                             : "=r"(done) : "r"(mb), "r"(parity) : "memory");
            } while (!done);
        }
        parity ^= 1;

        // -------- compute: 12 ck per quarter, tile 4b x 4o, b-paired f32x2 --------
        u64 acc[8];                            // [jbp*4? -> j: 0..3 = jbp0/m, 4..7 = jbp1/m]
        #pragma unroll
        for (int j = 0; j < 8; ++j) acc[j] = 0ull;

        #pragma unroll 4
        for (int cl = 0; cl < 12; ++cl) {
            const float* xr = slabf + ((kq * 12 + cl) * 4 + l) * 36 + bg * 4;
            ulonglong2 X0 = *(const ulonglong2*)(xr);        // kw=0: b pairs
            ulonglong2 X1 = *(const ulonglong2*)(xr + 36);   // kw=1
            ulonglong2 X2 = *(const ulonglong2*)(xr + 72);   // kw=2
            const float* wp = wpf + cl * 3;
            #pragma unroll
            for (int m = 0; m < 4; ++m) {
                float wa = wp[m * 584];
                float wb_ = wp[m * 584 + 1];
                float wc = wp[m * 584 + 2];
                u64 wau = pack2(wa), wbu = pack2(wb_), wcu = pack2(wc);
                fma2(acc[m],     X0.x, wau); fma2(acc[4 + m], X0.y, wau);
                fma2(acc[m],     X1.x, wbu); fma2(acc[4 + m], X1.y, wbu);
                fma2(acc[m],     X2.x, wcu); fma2(acc[4 + m], X2.y, wcu);
            }
        }
        __syncthreads();                       // all warps done reading w buf

        // -------- kq reduction in retired w buffer (4 slots x 256 u64 = 8KB) --------
        u64* slots = (u64*)sm;
        if (kq >= 2) {
            int s = oh * 2 + kq - 2;
            #pragma unroll
            for (int j = 0; j < 8; ++j)
                slots[s * 256 + j * 32 + lane] = acc[j];
        }
        __syncthreads();
        if (kq < 2) {
            int s = oh * 2 + kq;
            #pragma unroll
            for (int j = 0; j < 8; ++j)
                acc[j] = add2(acc[j], slots[s * 256 + j * 32 + lane]);
            if (kq == 1) {
                #pragma unroll
                for (int j = 0; j < 8; ++j)
                    slots[(oh * 2 + 1) * 256 + j * 32 + lane] = acc[j];
            }
        }
        __syncthreads();
        if (kq == 0) {
            #pragma unroll
            for (int j = 0; j < 8; ++j) {
                u64 s = add2(acc[j], slots[(oh * 2 + 1) * 256 + j * 32 + lane]);
                float lo, hi;
                unpackf2(s, lo, hi);
                int jbp = j >> 2, m = j & 3;
                int b = bg * 4 + jbp * 2;
                int o = oh * 16 + m * 4 + og;
                float bv = (m == 0) ? bv0 : (m == 1) ? bv1 : (m == 2) ? bv2 : bv3;
                out[(size_t)(b * 32 + o) * 4096 + loc]       = lo + bv;
                out[(size_t)((b + 1) * 32 + o) * 4096 + loc] = hi + bv;
            }
        }
        __syncthreads();                       // slots consumed

        // -------- DMA weights for loc1 into the (now free) buffer --------
        if (l == 0) {
            asm volatile("fence.proxy.async.shared::cta;" ::: "memory");
            if (tid < 32) {
                asm volatile("mbarrier.arrive.expect_tx.shared.b64 _, [%0], %1;"
                             :: "r"(mb), "r"(576) : "memory");
                const char* src = (const char*)weights + ((size_t)(loc0 + 1) * 32 + tid) * 576;
                unsigned dst = smbase + (tid >> 1) * 1168 + (tid & 1) * 576;
                asm volatile("cp.async.bulk.shared::cta.global.mbarrier::complete_tx::bytes "
                             "[%0], [%1], %2, [%3];"
                             :: "r"(dst), "l"(src), "r"(576), "r"(mb) : "memory");
            }
        }
    }
}

extern "C" void kernel_launch(void* const* d_in, const int* in_sizes, int n_in,
                              void* d_out, int out_size) {
    const float* x       = (const float*)d_in[0];
    const float* weights = (const float*)d_in[1];
    const float* bias    = (const float*)d_in[2];
    float* out = (float*)d_out;
    (void)in_sizes; (void)n_in; (void)out_size;

    cudaFuncSetAttribute(xonv_kernel, cudaFuncAttributeMaxDynamicSharedMemorySize, SMEM_B);
    xonv_kernel<<<GRID, THREADS, SMEM_B>>>(x, weights, bias, out);
}

// round 14
// speedup vs baseline: 2.2522x; 1.2646x over previous
#include <cuda_runtime.h>

typedef unsigned long long u64;

#define THREADS 256
#define GRID    2048

// ---- smem (bytes) ----
#define WBUF_B   18688          // paired o-rows: w(o,p) = (o>>1)*292 + (o&1)*144 + p (floats)
#define SLAB_OFF 18688          // slab: 192 rows (ck*4+col) x 36 floats
#define SLAB_B   27648
#define MB_OFF   (SLAB_OFF + SLAB_B)    // 46336
#define SMEM_B   (MB_OFF + 16)          // 46352 -> 4 CTAs/SM

// 16MB staging buffer: scratch[loc][s], s = oh*512 + j*64 + bg*8 + og*2 + pair
__device__ float g_scratch[4096 * 1024];

__device__ __forceinline__ void fma2(u64& d, u64 a, u64 b) {
    asm("fma.rn.f32x2 %0, %1, %2, %0;" : "+l"(d) : "l"(a), "l"(b));
}
__device__ __forceinline__ u64 add2(u64 a, u64 b) {
    u64 r; asm("add.rn.f32x2 %0, %1, %2;" : "=l"(r) : "l"(a), "l"(b)); return r;
}
__device__ __forceinline__ u64 pack2(float v) {
    u64 r; asm("mov.b64 %0, {%1, %1};" : "=l"(r) : "f"(v)); return r;
}
__device__ __forceinline__ void unpackf2(u64 d, float& lo, float& hi) {
    asm("mov.b64 {%0, %1}, %2;" : "=f"(lo), "=f"(hi) : "l"(d));
}
__device__ __forceinline__ unsigned smem_u32(const void* p) {
    unsigned a;
    asm("{ .reg .u64 t; cvta.to.shared.u64 t, %1; cvt.u32.u64 %0, t; }" : "=r"(a) : "l"(p));
    return a;
}

__global__ __launch_bounds__(THREADS, 4) void xonv_main(
    const float* __restrict__ x,        // (32, 16, 64, 64)
    const float* __restrict__ weights,  // (64, 64, 32, 16, 3, 3)
    const float* __restrict__ bias)     // (64, 64, 32)
{
    extern __shared__ __align__(16) char sm[];
    float* wsf   = (float*)sm;
    float* slabf = (float*)(sm + SLAB_OFF);
    const unsigned smbase = smem_u32(sm);
    const unsigned mb = smbase + MB_OFF;

    const int tid  = threadIdx.x;
    const int lane = tid & 31;
    const int wid  = tid >> 5;
    const int h    = blockIdx.x >> 5;
    const int w0   = (blockIdx.x & 31) * 2;
    const int loc0 = h * 64 + w0;

    if (tid == 0)
        asm volatile("mbarrier.init.shared.b64 [%0], %1;" :: "r"(mb), "r"(32) : "memory");
    __syncthreads();

    // -------- DMA weights for loc0 --------
    if (tid < 32) {
        asm volatile("mbarrier.arrive.expect_tx.shared.b64 _, [%0], %1;"
                     :: "r"(mb), "r"(576) : "memory");
        const char* src = (const char*)weights + ((size_t)loc0 * 32 + tid) * 576;
        unsigned dst = smbase + (tid >> 1) * 1168 + (tid & 1) * 576;
        asm volatile("cp.async.bulk.shared::cta.global.mbarrier::complete_tx::bytes "
                     "[%0], [%1], %2, [%3];"
                     :: "r"(dst), "l"(src), "r"(576), "r"(mb) : "memory");
    }

    // -------- stage shared x slab: rows (ck, col 0..3), cols = w0-1..w0+2 --------
    {
        const int dr = lane >> 2;
        const int c  = lane & 3;
        const int ww = w0 + c - 1;
        const bool wok = (unsigned)ww < 64u;
        #pragma unroll
        for (int itb = 0; itb < 4; ++itb) {
            const int b = itb * 8 + wid;
            const float* xb = x + (size_t)b * 65536;
            #pragma unroll
            for (int itc = 0; itc < 6; ++itc) {
                int ck = itc * 8 + dr;
                int ci = (ck * 683) >> 11;     // ck/3
                int kh = ck - ci * 3;
                int hh = h + kh - 1;
                float v = 0.f;
                if ((unsigned)hh < 64u && wok)
                    v = xb[ci * 4096 + hh * 64 + ww];
                slabf[(ck * 4 + c) * 36 + b] = v;
            }
        }
    }
    __syncthreads();

    const int kq = wid >> 1;                   // K quarter
    const int oh = wid & 1;                    // o half
    const int bg = lane >> 2;                  // b base = bg*4
    const int og = lane & 3;                   // o = oh*16 + m*4 + og

    const float* wpf = wsf + (oh * 8 + (og >> 1)) * 292 + (og & 1) * 144 + kq * 36;

    int parity = 0;
    #pragma unroll
    for (int l = 0; l < 2; ++l) {
        const int loc = loc0 + l;

        float bv0 = 0.f, bv1 = 0.f, bv2 = 0.f, bv3 = 0.f;
        if (kq == 0) {
            const float* bp = bias + (size_t)loc * 32 + oh * 16 + og;
            bv0 = bp[0]; bv1 = bp[4]; bv2 = bp[8]; bv3 = bp[12];
        }

        {   // wait this loc's weights
            unsigned done;
            do {
                asm volatile("{ .reg .pred p; mbarrier.try_wait.parity.shared.b64 p, [%1], %2; "
                             "selp.b32 %0, 1, 0, p; }"
                             : "=r"(done) : "r"(mb), "r"(parity) : "memory");
            } while (!done);
        }
        parity ^= 1;

        // -------- compute: 12 ck per quarter, tile 4b x 4o, b-paired f32x2 --------
        u64 acc[8];                            // j = jbp*4 + m
        #pragma unroll
        for (int j = 0; j < 8; ++j) acc[j] = 0ull;

        #pragma unroll 4
        for (int cl = 0; cl < 12; ++cl) {
            const float* xr = slabf + ((kq * 12 + cl) * 4 + l) * 36 + bg * 4;
            ulonglong2 X0 = *(const ulonglong2*)(xr);
            ulonglong2 X1 = *(const ulonglong2*)(xr + 36);
            ulonglong2 X2 = *(const ulonglong2*)(xr + 72);
            const float* wp = wpf + cl * 3;
            #pragma unroll
            for (int m = 0; m < 4; ++m) {
                float wa  = wp[m * 584];
                float wb_ = wp[m * 584 + 1];
                float wc  = wp[m * 584 + 2];
                u64 wau = pack2(wa), wbu = pack2(wb_), wcu = pack2(wc);
                fma2(acc[m],     X0.x, wau); fma2(acc[4 + m], X0.y, wau);
                fma2(acc[m],     X1.x, wbu); fma2(acc[4 + m], X1.y, wbu);
                fma2(acc[m],     X2.x, wcu); fma2(acc[4 + m], X2.y, wcu);
            }
        }
        __syncthreads();                       // w buf reads done

        // -------- kq reduction via slots in retired w buffer --------
        u64* slots = (u64*)sm;                 // 4 x 256 u64
        if (kq >= 2) {
            int s = oh * 2 + kq - 2;
            #pragma unroll
            for (int j = 0; j < 8; ++j)
                slots[s * 256 + j * 32 + lane] = acc[j];
        }
        __syncthreads();
        if (kq < 2) {
            int s = oh * 2 + kq;
            #pragma unroll
            for (int j = 0; j < 8; ++j)
                acc[j] = add2(acc[j], slots[s * 256 + j * 32 + lane]);
            if (kq == 1) {
                #pragma unroll
                for (int j = 0; j < 8; ++j)
                    slots[(oh * 2 + 1) * 256 + j * 32 + lane] = acc[j];
            }
        }
        __syncthreads();

        // -------- epilogue: coalesced float2 into permuted scratch --------
        if (kq == 0) {
            float* scr = g_scratch + (size_t)loc * 1024 + oh * 512 + bg * 8 + og * 2;
            #pragma unroll
            for (int j = 0; j < 8; ++j) {
                u64 s = add2(acc[j], slots[(oh * 2 + 1) * 256 + j * 32 + lane]);
                float lo, hi;
                unpackf2(s, lo, hi);
                int m = j & 3;
                float bv = (m == 0) ? bv0 : (m == 1) ? bv1 : (m == 2) ? bv2 : bv3;
                *(float2*)(scr + j * 64) = make_float2(lo + bv, hi + bv);
            }
        }
        __syncthreads();                       // slots consumed

        // -------- DMA weights for loc1 --------
        if (l == 0) {
            asm volatile("fence.proxy.async.shared::cta;" ::: "memory");
            if (tid < 32) {
                asm volatile("mbarrier.arrive.expect_tx.shared.b64 _, [%0], %1;"
                             :: "r"(mb), "r"(576) : "memory");
                const char* src = (const char*)weights + ((size_t)(loc0 + 1) * 32 + tid) * 576;
                unsigned dst = smbase + (tid >> 1) * 1168 + (tid & 1) * 576;
                asm volatile("cp.async.bulk.shared::cta.global.mbarrier::complete_tx::bytes "
                             "[%0], [%1], %2, [%3];"
                             :: "r"(dst), "l"(src), "r"(576), "r"(mb) : "memory");
            }
        }
    }
}

// un-permute + transpose: out[b][o][loc] = scratch[loc][s(b,o)]
__global__ __launch_bounds__(256) void xonv_transpose(float* __restrict__ out)
{
    __shared__ float tile[32 * 33];
    const int lane = threadIdx.x & 31;
    const int wid  = threadIdx.x >> 5;
    const int loc0 = (blockIdx.x & 127) * 32;
    const int s0   = (blockIdx.x >> 7) * 32;

    #pragma unroll
    for (int i = 0; i < 4; ++i) {
        int r = wid * 4 + i;                   // loc offset
        tile[lane * 33 + r] = g_scratch[(size_t)(loc0 + r) * 1024 + s0 + lane];
    }
    __syncthreads();
    #pragma unroll
    for (int i = 0; i < 4; ++i) {
        int sy = wid * 4 + i;
        int s  = s0 + sy;
        int pair = s & 1;
        int og   = (s >> 1) & 3;
        int bg   = (s >> 3) & 7;
        int j    = (s >> 6) & 7;
        int ohh  = (s >> 9) & 1;
        int b = bg * 4 + (j >> 2) * 2 + pair;
        int o = ohh * 16 + (j & 3) * 4 + og;
        out[(size_t)(b * 32 + o) * 4096 + loc0 + lane] = tile[sy * 33 + lane];
    }
}

extern "C" void kernel_launch(void* const* d_in, const int* in_sizes, int n_in,
                              void* d_out, int out_size) {
    const float* x       = (const float*)d_in[0];
    const float* weights = (const float*)d_in[1];
    const float* bias    = (const float*)d_in[2];
    float* out = (float*)d_out;
    (void)in_sizes; (void)n_in; (void)out_size;

    cudaFuncSetAttribute(xonv_main, cudaFuncAttributeMaxDynamicSharedMemorySize, SMEM_B);
    xonv_main<<<GRID, THREADS, SMEM_B>>>(x, weights, bias);
    xonv_transpose<<<4096, 256>>>(out);
}